// round 1
// baseline (speedup 1.0000x reference)
#include <cuda_runtime.h>

#define HID 64
#define G3  192     // 3*H
#define BB  512
#define TT  1024
#define NB  4       // batch rows per CTA in recurrence
#define GEMM_ROWS 128

// ---------------- scratch (device globals; no allocations) ----------------
__device__ float g_xg[(size_t)BB * TT * G3];   // 402 MB
__device__ float g_hA[(size_t)BB * TT * HID];  // 134 MB
__device__ float g_hB[(size_t)BB * TT * HID];  // 134 MB

__device__ __forceinline__ float fsig(float x) {
    return __fdividef(1.0f, 1.0f + __expf(-x));
}
__device__ __forceinline__ float ftanh_fast(float x) {
    float e = __expf(-2.0f * x);
    return __fdividef(1.0f - e, 1.0f + e);
}

// ---------------- layer-0 input pre-activations (K=5, memory bound) -------
__global__ __launch_bounds__(192) void xg0_kernel(
    const float* __restrict__ x, const float* __restrict__ w,
    const float* __restrict__ b)
{
    __shared__ float ws[G3 * 5];
    __shared__ float bs[G3];
    __shared__ float xs[8][5];
    int g = threadIdx.x;                  // 0..191
    for (int i = g; i < G3 * 5; i += 192) ws[i] = w[i];
    if (g < G3) bs[g] = b[g];
    size_t row0 = (size_t)blockIdx.x * 8;
    if (g < 40) xs[g / 5][g % 5] = x[row0 * 5 + g];
    __syncthreads();
#pragma unroll
    for (int r = 0; r < 8; r++) {
        float acc = bs[g];
#pragma unroll
        for (int i = 0; i < 5; i++) acc += xs[r][i] * ws[g * 5 + i];
        g_xg[(row0 + r) * G3 + g] = acc;
    }
}

// ---------------- xg GEMM for layers 1..4: [BT,64]x[64,192]+b -------------
__global__ __launch_bounds__(192) void xg_gemm_kernel(
    int insel, const float* __restrict__ w, const float* __restrict__ bias)
{
    const float* __restrict__ hin = insel ? g_hB : g_hA;
    __shared__ __align__(16) float hs[GEMM_ROWS][HID];  // 32 KB
    int g = threadIdx.x;                  // output column 0..191
    float wr[HID];
#pragma unroll
    for (int k = 0; k < 16; k++)
        *(float4*)&wr[k * 4] = *(const float4*)&w[g * HID + k * 4];
    float bv = bias[g];

    size_t row0 = (size_t)blockIdx.x * GEMM_ROWS;
    const float4* src = (const float4*)&hin[row0 * HID];
    float4* dst = (float4*)&hs[0][0];
    for (int i = g; i < GEMM_ROWS * HID / 4; i += 192) dst[i] = src[i];
    __syncthreads();

#pragma unroll 2
    for (int r = 0; r < GEMM_ROWS; r++) {
        float acc = bv;
#pragma unroll
        for (int k = 0; k < 16; k++) {
            float4 h4 = *(const float4*)&hs[r][k * 4];
            acc += wr[4 * k + 0] * h4.x + wr[4 * k + 1] * h4.y
                 + wr[4 * k + 2] * h4.z + wr[4 * k + 3] * h4.w;
        }
        g_xg[(row0 + r) * G3 + g] = acc;
    }
}

// ---------------- recurrence: one CTA = NB batch rows, all T steps --------
__global__ __launch_bounds__(192) void rec_kernel(
    const float* __restrict__ whh, const float* __restrict__ bhh, int outsel)
{
    float* __restrict__ hout = outsel ? g_hB : g_hA;
    __shared__ __align__(16) float h_sh[NB][HID];
    __shared__ float r_sh[NB][HID];
    __shared__ float z_sh[NB][HID];
    int g = threadIdx.x;                  // gate row 0..191
    int b0 = blockIdx.x * NB;

    float wr[HID];
#pragma unroll
    for (int k = 0; k < 16; k++)
        *(float4*)&wr[k * 4] = *(const float4*)&whh[g * HID + k * 4];
    float bv = bhh[g];

    for (int i = g; i < NB * HID; i += 192) ((float*)h_sh)[i] = 0.0f;

    // prefetch xg for t=0
    float xc[NB];
#pragma unroll
    for (int nb = 0; nb < NB; nb++)
        xc[nb] = g_xg[((size_t)(b0 + nb) * TT) * G3 + g];
    __syncthreads();

    for (int t = 0; t < TT; t++) {
        float xn[NB];
        if (t + 1 < TT) {
#pragma unroll
            for (int nb = 0; nb < NB; nb++)
                xn[nb] = g_xg[((size_t)(b0 + nb) * TT + (t + 1)) * G3 + g];
        } else {
#pragma unroll
            for (int nb = 0; nb < NB; nb++) xn[nb] = 0.0f;
        }

        float gh[NB];
#pragma unroll
        for (int nb = 0; nb < NB; nb++) {
            float acc = bv;
#pragma unroll
            for (int k = 0; k < 16; k++) {
                float4 h4 = *(const float4*)&h_sh[nb][k * 4];
                acc += wr[4 * k + 0] * h4.x + wr[4 * k + 1] * h4.y
                     + wr[4 * k + 2] * h4.z + wr[4 * k + 3] * h4.w;
            }
            gh[nb] = acc;
        }

        if (g < HID) {                       // r gate rows
#pragma unroll
            for (int nb = 0; nb < NB; nb++)
                r_sh[nb][g] = fsig(xc[nb] + gh[nb]);
        } else if (g < 2 * HID) {            // z gate rows
#pragma unroll
            for (int nb = 0; nb < NB; nb++)
                z_sh[nb][g - HID] = fsig(xc[nb] + gh[nb]);
        }
        __syncthreads();

        if (g >= 2 * HID) {                  // n gate rows -> h update
            int j = g - 2 * HID;
#pragma unroll
            for (int nb = 0; nb < NB; nb++) {
                float n  = ftanh_fast(xc[nb] + r_sh[nb][j] * gh[nb]);
                float z  = z_sh[nb][j];
                float hp = h_sh[nb][j];
                float hn = n + z * (hp - n);
                h_sh[nb][j] = hn;
                hout[((size_t)(b0 + nb) * TT + t) * HID + j] = hn;
            }
        }
        __syncthreads();
#pragma unroll
        for (int nb = 0; nb < NB; nb++) xc[nb] = xn[nb];
    }
}

// ---------------- final FC on last timestep -------------------------------
__global__ void fc_kernel(int insel, const float* __restrict__ wfc,
                          const float* __restrict__ bfc, float* __restrict__ out)
{
    const float* __restrict__ hin = insel ? g_hB : g_hA;
    int b = blockIdx.x;
    int j = threadIdx.x;                   // 64
    __shared__ float s[64];
    s[j] = hin[((size_t)b * TT + (TT - 1)) * HID + j] * wfc[j];
    __syncthreads();
    if (j < 32) {
        float a = s[j] + s[j + 32];
        for (int o = 16; o > 0; o >>= 1) a += __shfl_down_sync(0xffffffff, a, o);
        if (j == 0) out[b] = a + bfc[0];
    }
}

// ---------------- launch ---------------------------------------------------
extern "C" void kernel_launch(void* const* d_in, const int* in_sizes, int n_in,
                              void* d_out, int out_size)
{
    const float* x     = (const float*)d_in[0];
    const float* w_ih0 = (const float*)d_in[1];
    const float* w_hh0 = (const float*)d_in[2];
    const float* b_ih0 = (const float*)d_in[3];
    const float* b_hh0 = (const float*)d_in[4];
    const float* w_ih  = (const float*)d_in[5];
    const float* w_hh  = (const float*)d_in[6];
    const float* b_ih  = (const float*)d_in[7];
    const float* b_hh  = (const float*)d_in[8];
    const float* w_fc  = (const float*)d_in[9];
    const float* b_fc  = (const float*)d_in[10];
    float* out = (float*)d_out;

    // layer 0
    xg0_kernel<<<(BB * TT) / 8, 192>>>(x, w_ih0, b_ih0);
    rec_kernel<<<BB / NB, 192>>>(w_hh0, b_hh0, /*outsel=*/0);   // -> A

    // layers 1..4: xg GEMM then recurrence, ping-ponging A/B
    int insel = 0;
    for (int l = 0; l < 4; l++) {
        xg_gemm_kernel<<<(BB * TT) / GEMM_ROWS, 192>>>(
            insel, w_ih + (size_t)l * G3 * HID, b_ih + (size_t)l * G3);
        int outsel = insel ^ 1;
        rec_kernel<<<BB / NB, 192>>>(
            w_hh + (size_t)l * G3 * HID, b_hh + (size_t)l * G3, outsel);
        insel = outsel;
    }

    fc_kernel<<<BB, 64>>>(insel, w_fc, b_fc, out);
}

// round 2
// speedup vs baseline: 1.5137x; 1.5137x over previous
#include <cuda_runtime.h>

#define HID 64
#define G3  192     // 3*H
#define BB  512
#define TT  1024
#define GEMM_ROWS 128

// ---------------- scratch (device globals; no allocations) ----------------
__device__ float g_xg[(size_t)BB * TT * G3];   // 402 MB
__device__ float g_hA[(size_t)BB * TT * HID];  // 134 MB
__device__ float g_hB[(size_t)BB * TT * HID];  // 134 MB

typedef unsigned long long u64;

__device__ __forceinline__ void ffma2(u64& acc, u64 a, u64 b) {
    asm("fma.rn.f32x2 %0, %1, %2, %0;" : "+l"(acc) : "l"(a), "l"(b));
}
__device__ __forceinline__ float hsum2(u64 v) {
    float lo, hi;
    asm("mov.b64 {%0, %1}, %2;" : "=f"(lo), "=f"(hi) : "l"(v));
    return lo + hi;
}

__device__ __forceinline__ float fsig(float x) {
    return __fdividef(1.0f, 1.0f + __expf(-x));
}
__device__ __forceinline__ float ftanh_fast(float x) {
    float e = __expf(-2.0f * x);
    return __fdividef(1.0f - e, 1.0f + e);
}

// ---------------- layer-0 input pre-activations (K=5, memory bound) -------
__global__ __launch_bounds__(192) void xg0_kernel(
    const float* __restrict__ x, const float* __restrict__ w,
    const float* __restrict__ b)
{
    __shared__ float ws[G3 * 5];
    __shared__ float bs[G3];
    __shared__ float xs[8][5];
    int g = threadIdx.x;                  // 0..191
    for (int i = g; i < G3 * 5; i += 192) ws[i] = w[i];
    if (g < G3) bs[g] = b[g];
    size_t row0 = (size_t)blockIdx.x * 8;
    if (g < 40) xs[g / 5][g % 5] = x[row0 * 5 + g];
    __syncthreads();
#pragma unroll
    for (int r = 0; r < 8; r++) {
        float acc = bs[g];
#pragma unroll
        for (int i = 0; i < 5; i++) acc += xs[r][i] * ws[g * 5 + i];
        g_xg[(row0 + r) * G3 + g] = acc;
    }
}

// ---------------- xg GEMM for layers 1..4: [BT,64]x[64,192]+b -------------
// f32x2 packed along K (w and h pairs are contiguous -> no transpose needed)
__global__ __launch_bounds__(192) void xg_gemm_kernel(
    int insel, const float* __restrict__ w, const float* __restrict__ bias)
{
    const float* __restrict__ hin = insel ? g_hB : g_hA;
    __shared__ __align__(16) float hs[GEMM_ROWS][HID];  // 32 KB
    int g = threadIdx.x;                  // output column 0..191

    u64 wv[32];                            // packed (w[2k], w[2k+1])
    const ulonglong2* wrow = (const ulonglong2*)&w[g * HID];
#pragma unroll
    for (int q = 0; q < 16; q++) {
        ulonglong2 v = wrow[q];
        wv[2 * q] = v.x; wv[2 * q + 1] = v.y;
    }
    float bv = bias[g];

    size_t row0 = (size_t)blockIdx.x * GEMM_ROWS;
    const float4* src = (const float4*)&hin[row0 * HID];
    float4* dst = (float4*)&hs[0][0];
    for (int i = g; i < GEMM_ROWS * HID / 4; i += 192) dst[i] = src[i];
    __syncthreads();

#pragma unroll 2
    for (int r = 0; r < GEMM_ROWS; r++) {
        u64 acc0 = 0, acc1 = 0;
        const ulonglong2* hrow = (const ulonglong2*)&hs[r][0];
#pragma unroll
        for (int q = 0; q < 16; q++) {
            ulonglong2 hv = hrow[q];            // LDS.128 broadcast
            ffma2(acc0, wv[2 * q], hv.x);
            ffma2(acc1, wv[2 * q + 1], hv.y);
        }
        g_xg[(row0 + r) * G3 + g] = bv + hsum2(acc0) + hsum2(acc1);
    }
}

// ---------------- recurrence: 384 thr = 2 groups x (192 thr, 2 batch) -----
__global__ __launch_bounds__(384, 1) void rec_kernel(
    const float* __restrict__ whh, const float* __restrict__ bhh, int outsel)
{
    float* __restrict__ hout = outsel ? g_hB : g_hA;
    __shared__ __align__(16) float h_sh[4][HID];
    __shared__ float r_sh[4][HID];
    __shared__ float z_sh[4][HID];

    int tid = threadIdx.x;
    int grp = tid / 192;                  // 0 or 1
    int g   = tid % 192;                  // gate row
    int nb0 = grp * 2;                    // CTA-local batch index base
    int b0  = blockIdx.x * 4 + nb0;       // global batch base (2 rows)

    u64 wv[32];
    const ulonglong2* wrow = (const ulonglong2*)&whh[g * HID];
#pragma unroll
    for (int q = 0; q < 16; q++) {
        ulonglong2 v = wrow[q];
        wv[2 * q] = v.x; wv[2 * q + 1] = v.y;
    }
    float bv = bhh[g];

    for (int i = tid; i < 4 * HID; i += 384) ((float*)h_sh)[i] = 0.0f;

    // prefetch xg for t=0
    float xc[2];
#pragma unroll
    for (int l = 0; l < 2; l++)
        xc[l] = g_xg[((size_t)(b0 + l) * TT) * G3 + g];
    __syncthreads();

    int barid = grp + 1;

    for (int t = 0; t < TT; t++) {
        float xn[2];
        if (t + 1 < TT) {
#pragma unroll
            for (int l = 0; l < 2; l++)
                xn[l] = g_xg[((size_t)(b0 + l) * TT + (t + 1)) * G3 + g];
        } else {
            xn[0] = xn[1] = 0.0f;
        }

        float gh[2];
#pragma unroll
        for (int l = 0; l < 2; l++) {
            u64 acc0 = 0, acc1 = 0;
            const ulonglong2* hrow = (const ulonglong2*)&h_sh[nb0 + l][0];
#pragma unroll
            for (int q = 0; q < 16; q++) {
                ulonglong2 hv = hrow[q];        // LDS.128 broadcast
                ffma2(acc0, wv[2 * q], hv.x);
                ffma2(acc1, wv[2 * q + 1], hv.y);
            }
            gh[l] = bv + hsum2(acc0) + hsum2(acc1);
        }

        if (g < HID) {                       // r gate rows
#pragma unroll
            for (int l = 0; l < 2; l++)
                r_sh[nb0 + l][g] = fsig(xc[l] + gh[l]);
        } else if (g < 2 * HID) {            // z gate rows
#pragma unroll
            for (int l = 0; l < 2; l++)
                z_sh[nb0 + l][g - HID] = fsig(xc[l] + gh[l]);
        }
        asm volatile("bar.sync %0, 192;" :: "r"(barid) : "memory");

        if (g >= 2 * HID) {                  // n gate rows -> h update
            int j = g - 2 * HID;
#pragma unroll
            for (int l = 0; l < 2; l++) {
                float n  = ftanh_fast(xc[l] + r_sh[nb0 + l][j] * gh[l]);
                float z  = z_sh[nb0 + l][j];
                float hp = h_sh[nb0 + l][j];
                float hn = n + z * (hp - n);
                h_sh[nb0 + l][j] = hn;
                hout[((size_t)(b0 + l) * TT + t) * HID + j] = hn;
            }
        }
        asm volatile("bar.sync %0, 192;" :: "r"(barid) : "memory");

        xc[0] = xn[0]; xc[1] = xn[1];
    }
}

// ---------------- final FC on last timestep -------------------------------
__global__ void fc_kernel(int insel, const float* __restrict__ wfc,
                          const float* __restrict__ bfc, float* __restrict__ out)
{
    const float* __restrict__ hin = insel ? g_hB : g_hA;
    int b = blockIdx.x;
    int j = threadIdx.x;                   // 64
    __shared__ float s[64];
    s[j] = hin[((size_t)b * TT + (TT - 1)) * HID + j] * wfc[j];
    __syncthreads();
    if (j < 32) {
        float a = s[j] + s[j + 32];
        for (int o = 16; o > 0; o >>= 1) a += __shfl_down_sync(0xffffffff, a, o);
        if (j == 0) out[b] = a + bfc[0];
    }
}

// ---------------- launch ---------------------------------------------------
extern "C" void kernel_launch(void* const* d_in, const int* in_sizes, int n_in,
                              void* d_out, int out_size)
{
    const float* x     = (const float*)d_in[0];
    const float* w_ih0 = (const float*)d_in[1];
    const float* w_hh0 = (const float*)d_in[2];
    const float* b_ih0 = (const float*)d_in[3];
    const float* b_hh0 = (const float*)d_in[4];
    const float* w_ih  = (const float*)d_in[5];
    const float* w_hh  = (const float*)d_in[6];
    const float* b_ih  = (const float*)d_in[7];
    const float* b_hh  = (const float*)d_in[8];
    const float* w_fc  = (const float*)d_in[9];
    const float* b_fc  = (const float*)d_in[10];
    float* out = (float*)d_out;

    // layer 0
    xg0_kernel<<<(BB * TT) / 8, 192>>>(x, w_ih0, b_ih0);
    rec_kernel<<<BB / 4, 384>>>(w_hh0, b_hh0, /*outsel=*/0);   // -> A

    // layers 1..4: xg GEMM then recurrence, ping-ponging A/B
    int insel = 0;
    for (int l = 0; l < 4; l++) {
        xg_gemm_kernel<<<(BB * TT) / GEMM_ROWS, 192>>>(
            insel, w_ih + (size_t)l * G3 * HID, b_ih + (size_t)l * G3);
        int outsel = insel ^ 1;
        rec_kernel<<<BB / 4, 384>>>(
            w_hh + (size_t)l * G3 * HID, b_hh + (size_t)l * G3, outsel);
        insel = outsel;
    }

    fc_kernel<<<BB, 64>>>(insel, w_fc, b_fc, out);
}

// round 3
// speedup vs baseline: 1.8269x; 1.2069x over previous
#include <cuda_runtime.h>

#define HID 64
#define G3  192     // 3*H
#define BB  512
#define TT  1024
#define GEMM_ROWS 128

// ---------------- scratch (device globals; no allocations) ----------------
__device__ float g_xg[(size_t)BB * TT * G3];   // 402 MB
__device__ float g_hA[(size_t)BB * TT * HID];  // 134 MB
__device__ float g_hB[(size_t)BB * TT * HID];  // 134 MB

typedef unsigned long long u64;

__device__ __forceinline__ void ffma2(u64& acc, u64 a, u64 b) {
    asm("fma.rn.f32x2 %0, %1, %2, %0;" : "+l"(acc) : "l"(a), "l"(b));
}
__device__ __forceinline__ float hsum2(u64 v) {
    float lo, hi;
    asm("mov.b64 {%0, %1}, %2;" : "=f"(lo), "=f"(hi) : "l"(v));
    return lo + hi;
}

__device__ __forceinline__ float fsig(float x) {
    return __fdividef(1.0f, 1.0f + __expf(-x));
}
__device__ __forceinline__ float ftanh_fast(float x) {
    float e = __expf(-2.0f * x);
    return __fdividef(1.0f - e, 1.0f + e);
}

// ---------------- layer-0 input pre-activations (K=5, memory bound) -------
__global__ __launch_bounds__(192) void xg0_kernel(
    const float* __restrict__ x, const float* __restrict__ w,
    const float* __restrict__ b)
{
    __shared__ float ws[G3 * 5];
    __shared__ float bs[G3];
    __shared__ float xs[8][5];
    int g = threadIdx.x;                  // 0..191
    for (int i = g; i < G3 * 5; i += 192) ws[i] = w[i];
    if (g < G3) bs[g] = b[g];
    size_t row0 = (size_t)blockIdx.x * 8;
    if (g < 40) xs[g / 5][g % 5] = x[row0 * 5 + g];
    __syncthreads();
#pragma unroll
    for (int r = 0; r < 8; r++) {
        float acc = bs[g];
#pragma unroll
        for (int i = 0; i < 5; i++) acc += xs[r][i] * ws[g * 5 + i];
        g_xg[(row0 + r) * G3 + g] = acc;
    }
}

// ---------------- xg GEMM for layers 1..4: [BT,64]x[64,192]+b -------------
__global__ __launch_bounds__(192) void xg_gemm_kernel(
    int insel, const float* __restrict__ w, const float* __restrict__ bias)
{
    const float* __restrict__ hin = insel ? g_hB : g_hA;
    __shared__ __align__(16) float hs[GEMM_ROWS][HID];  // 32 KB
    int g = threadIdx.x;                  // output column 0..191

    u64 wv[32];                            // packed (w[2k], w[2k+1])
    const ulonglong2* wrow = (const ulonglong2*)&w[g * HID];
#pragma unroll
    for (int q = 0; q < 16; q++) {
        ulonglong2 v = wrow[q];
        wv[2 * q] = v.x; wv[2 * q + 1] = v.y;
    }
    float bv = bias[g];

    size_t row0 = (size_t)blockIdx.x * GEMM_ROWS;
    const float4* src = (const float4*)&hin[row0 * HID];
    float4* dst = (float4*)&hs[0][0];
    for (int i = g; i < GEMM_ROWS * HID / 4; i += 192) dst[i] = src[i];
    __syncthreads();

#pragma unroll 2
    for (int r = 0; r < GEMM_ROWS; r++) {
        u64 acc0 = 0, acc1 = 0;
        const ulonglong2* hrow = (const ulonglong2*)&hs[r][0];
#pragma unroll
        for (int q = 0; q < 16; q++) {
            ulonglong2 hv = hrow[q];            // LDS.128 broadcast
            ffma2(acc0, wv[2 * q], hv.x);
            ffma2(acc1, wv[2 * q + 1], hv.y);
        }
        g_xg[(row0 + r) * G3 + g] = bv + hsum2(acc0) + hsum2(acc1);
    }
}

// ---------------- recurrence: 1 thread = 1 hidden unit, all 3 gates -------
// 256 thr = 4 groups x 64 thr; group owns one batch row for all T steps.
// One 64-thread named barrier per step; no gate exchange through smem.
__global__ void __launch_bounds__(256, 1) rec_kernel(
    const float* __restrict__ whh, const float* __restrict__ bhh,
    int outsel, int write_all)
{
    float* __restrict__ hout = outsel ? g_hB : g_hA;
    __shared__ __align__(16) float hbuf[2][4][HID];   // double-buffered h

    int tid = threadIdx.x;
    int grp = tid >> 6;                   // 0..3 (batch row within CTA)
    int j   = tid & 63;                   // hidden unit
    int b   = blockIdx.x * 4 + grp;
    int barid = grp + 1;

    // weights: rows j (r), 64+j (z), 128+j (n), each 64 floats packed in u64
    u64 wr[32], wz[32], wn[32];
    {
        const ulonglong2* rr = (const ulonglong2*)&whh[(size_t)j * HID];
        const ulonglong2* rz = (const ulonglong2*)&whh[(size_t)(HID + j) * HID];
        const ulonglong2* rn = (const ulonglong2*)&whh[(size_t)(2 * HID + j) * HID];
#pragma unroll
        for (int q = 0; q < 16; q++) {
            ulonglong2 a = rr[q]; wr[2 * q] = a.x; wr[2 * q + 1] = a.y;
            ulonglong2 c = rz[q]; wz[2 * q] = c.x; wz[2 * q + 1] = c.y;
            ulonglong2 d = rn[q]; wn[2 * q] = d.x; wn[2 * q + 1] = d.y;
        }
    }
    float br = bhh[j], bz = bhh[HID + j], bn = bhh[2 * HID + j];

    hbuf[0][grp][j] = 0.0f;
    float hprev = 0.0f;

    const float* xgp = &g_xg[(size_t)b * TT * G3];
    // xg for t=0
    float xr = xgp[j], xz = xgp[HID + j], xn0 = xgp[2 * HID + j];

    asm volatile("bar.sync %0, 64;" :: "r"(barid) : "memory");

    int p = 0;
    for (int t = 0; t < TT; t++) {
        // prefetch xg for t+1
        float xr_n = 0.f, xz_n = 0.f, xn_n = 0.f;
        if (t + 1 < TT) {
            const float* xq = xgp + (size_t)(t + 1) * G3;
            xr_n = xq[j]; xz_n = xq[HID + j]; xn_n = xq[2 * HID + j];
        }

        // gh matvec for all three gates (h broadcast from smem)
        u64 ar0 = 0, ar1 = 0, az0 = 0, az1 = 0, an0 = 0, an1 = 0;
        const ulonglong2* hrow = (const ulonglong2*)&hbuf[p][grp][0];
#pragma unroll
        for (int q = 0; q < 16; q++) {
            ulonglong2 hv = hrow[q];              // LDS.128 broadcast
            ffma2(ar0, wr[2 * q], hv.x);
            ffma2(ar1, wr[2 * q + 1], hv.y);
            ffma2(az0, wz[2 * q], hv.x);
            ffma2(az1, wz[2 * q + 1], hv.y);
            ffma2(an0, wn[2 * q], hv.x);
            ffma2(an1, wn[2 * q + 1], hv.y);
        }
        float ghr = br + hsum2(ar0) + hsum2(ar1);
        float ghz = bz + hsum2(az0) + hsum2(az1);
        float ghn = bn + hsum2(an0) + hsum2(an1);

        float r = fsig(xr + ghr);
        float z = fsig(xz + ghz);
        float n = ftanh_fast(xn0 + r * ghn);
        float hn = n + z * (hprev - n);

        hbuf[p ^ 1][grp][j] = hn;
        hprev = hn;
        if (write_all || t == TT - 1)
            hout[((size_t)b * TT + t) * HID + j] = hn;

        asm volatile("bar.sync %0, 64;" :: "r"(barid) : "memory");
        p ^= 1;
        xr = xr_n; xz = xz_n; xn0 = xn_n;
    }
}

// ---------------- final FC on last timestep -------------------------------
__global__ void fc_kernel(int insel, const float* __restrict__ wfc,
                          const float* __restrict__ bfc, float* __restrict__ out)
{
    const float* __restrict__ hin = insel ? g_hB : g_hA;
    int b = blockIdx.x;
    int j = threadIdx.x;                   // 64
    __shared__ float s[64];
    s[j] = hin[((size_t)b * TT + (TT - 1)) * HID + j] * wfc[j];
    __syncthreads();
    if (j < 32) {
        float a = s[j] + s[j + 32];
        for (int o = 16; o > 0; o >>= 1) a += __shfl_down_sync(0xffffffff, a, o);
        if (j == 0) out[b] = a + bfc[0];
    }
}

// ---------------- launch ---------------------------------------------------
extern "C" void kernel_launch(void* const* d_in, const int* in_sizes, int n_in,
                              void* d_out, int out_size)
{
    const float* x     = (const float*)d_in[0];
    const float* w_ih0 = (const float*)d_in[1];
    const float* w_hh0 = (const float*)d_in[2];
    const float* b_ih0 = (const float*)d_in[3];
    const float* b_hh0 = (const float*)d_in[4];
    const float* w_ih  = (const float*)d_in[5];
    const float* w_hh  = (const float*)d_in[6];
    const float* b_ih  = (const float*)d_in[7];
    const float* b_hh  = (const float*)d_in[8];
    const float* w_fc  = (const float*)d_in[9];
    const float* b_fc  = (const float*)d_in[10];
    float* out = (float*)d_out;

    // layer 0
    xg0_kernel<<<(BB * TT) / 8, 192>>>(x, w_ih0, b_ih0);
    rec_kernel<<<BB / 4, 256>>>(w_hh0, b_hh0, /*outsel=*/0, /*write_all=*/1);

    // layers 1..4: xg GEMM then recurrence, ping-ponging A/B
    int insel = 0;
    for (int l = 0; l < 4; l++) {
        xg_gemm_kernel<<<(BB * TT) / GEMM_ROWS, 192>>>(
            insel, w_ih + (size_t)l * G3 * HID, b_ih + (size_t)l * G3);
        int outsel = insel ^ 1;
        int write_all = (l < 3) ? 1 : 0;   // last layer: only t = TT-1 needed
        rec_kernel<<<BB / 4, 256>>>(
            w_hh + (size_t)l * G3 * HID, b_hh + (size_t)l * G3, outsel, write_all);
        insel = outsel;
    }

    fc_kernel<<<BB, 64>>>(insel, w_fc, b_fc, out);
}